// round 1
// baseline (speedup 1.0000x reference)
#include <cuda_runtime.h>
#include <math.h>

#define N 4096
#define NN (4096ULL*4096ULL)

// ---------------- scratch (device globals; no runtime allocation) ----------------
__device__ float2 g_bufA[NN];        // 128 MB: after row FFT (pass 1)
__device__ float2 g_bufB[NN];        // 128 MB: transposed
__device__ float  g_img[NN];         // 64 MB: real spatial image (TRANSPOSED orientation)
__device__ float  g_c1[1365*1365];
__device__ float  g_c2[455*455];
__device__ float  g_c3[151*151];
__device__ float  g_c4[50*50];
__device__ float  g_c5[256];
__device__ float2 g_tw[1024];        // W[k] = exp(+2*pi*i*k/4096), k<1024 (only p*s<1024 used)

// ---------------- complex helpers ----------------
__device__ __forceinline__ float2 cmul(float2 a, float2 b) {
    return make_float2(fmaf(a.x, b.x, -a.y * b.y), fmaf(a.x, b.y, a.y * b.x));
}
__device__ __forceinline__ float2 cadd(float2 a, float2 b) { return make_float2(a.x + b.x, a.y + b.y); }
__device__ __forceinline__ float2 csub(float2 a, float2 b) { return make_float2(a.x - b.x, a.y - b.y); }

// ---------------- twiddle init ----------------
__global__ void twiddle_init() {
    int k = threadIdx.x;  // 1024 threads
    double ang = 6.283185307179586476925286766559 * (double)k / 4096.0;
    g_tw[k] = make_float2((float)cos(ang), (float)sin(ang));
}

// ---------------- Stockham radix-4 inverse FFT, N=4096, in shared memory ----------------
// 1024 threads, one butterfly per thread per stage. Result ends in s0 (6 stages = even).
// Inverse convention: X[k] = sum_j x[j] * exp(+2*pi*i*j*k/N)  (unnormalized).
__device__ __forceinline__ void fft4096_inv(float2* s0, float2* s1, int t)
{
    float2* in  = s0;
    float2* out = s1;
#pragma unroll
    for (int stage = 0; stage < 6; stage++) {
        const int s  = 1 << (2 * stage);
        const int q  = t & (s - 1);
        const int ps = t - q;                 // p*s  (< 1024)
        float2 a = in[t];
        float2 b = in[t + 1024];
        float2 c = in[t + 2048];
        float2 d = in[t + 3072];
        float2 w1 = g_tw[ps];
        float2 w2 = cmul(w1, w1);
        float2 w3 = cmul(w2, w1);
        float2 apc = cadd(a, c), amc = csub(a, c);
        float2 bpd = cadd(b, d), bmd = csub(b, d);
        float2 ib  = make_float2(-bmd.y, bmd.x);     // i*(b-d)
        int ob = q + 4 * ps;                          // q + s*4p
        out[ob]         = cadd(apc, bpd);
        out[ob + s]     = cmul(w1, cadd(amc, ib));
        out[ob + 2*s]   = cmul(w2, csub(apc, bpd));
        out[ob + 3*s]   = cmul(w3, csub(amc, ib));
        __syncthreads();
        float2* tmp = in; in = out; out = tmp;
    }
}

// ---------------- pass 1: elementwise (mag/phase) fused + row IFFT along axis -1 ----------------
__global__ void __launch_bounds__(1024, 2)
fft_pass1(const float* __restrict__ xr, const float* __restrict__ xi,
          const float* __restrict__ mk, const float* __restrict__ pk)
{
    extern __shared__ float2 sm[];
    float2* s0 = sm;
    float2* s1 = sm + 4096;
    const int row = blockIdx.x;        // k1
    const int t   = threadIdx.x;
    const size_t base = (size_t)row * N;
#pragma unroll
    for (int e = 0; e < 4; e++) {
        int idx = t + e * 1024;
        float a = xr[base + idx];
        float b = xi[base + idx];
        float m = sqrtf(fmaf(a, a, b * b)) * mk[base + idx];
        float p = atan2f(b, a) * pk[base + idx];
        float sp, cp;
        sincosf(p, &sp, &cp);
        s0[idx] = make_float2(m * cp, m * sp);
    }
    __syncthreads();
    fft4096_inv(s0, s1, t);
#pragma unroll
    for (int e = 0; e < 4; e++) {
        int idx = t + e * 1024;
        g_bufA[base + idx] = s0[idx];
    }
}

// ---------------- complex transpose (32x32 tiles) ----------------
__global__ void transpose_c()
{
    __shared__ float2 tile[32][33];
    int x  = blockIdx.x * 32 + threadIdx.x;
    int y0 = blockIdx.y * 32;
#pragma unroll
    for (int j = threadIdx.y; j < 32; j += 8)
        tile[j][threadIdx.x] = g_bufA[(size_t)(y0 + j) * N + x];
    __syncthreads();
    int x2 = blockIdx.y * 32 + threadIdx.x;
    int y2 = blockIdx.x * 32;
#pragma unroll
    for (int j = threadIdx.y; j < 32; j += 8)
        g_bufB[(size_t)(y2 + j) * N + x2] = tile[threadIdx.x][j];
}

// ---------------- pass 2: IFFT along original axis -2, write real part ----------------
// Input g_bufB[n2][k1]; output g_img[n2][n1] (transposed spatial image),
// scaled by 1/N^2 and (-1)^(n1+n2) (the folded ifftshift).
__global__ void __launch_bounds__(1024, 2)
fft_pass2()
{
    extern __shared__ float2 sm[];
    float2* s0 = sm;
    float2* s1 = sm + 4096;
    const int row = blockIdx.x;        // n2
    const int t   = threadIdx.x;
    const size_t base = (size_t)row * N;
#pragma unroll
    for (int e = 0; e < 4; e++) {
        int idx = t + e * 1024;
        s0[idx] = g_bufB[base + idx];
    }
    __syncthreads();
    fft4096_inv(s0, s1, t);
    const float scale = 1.0f / 16777216.0f;   // 1/N^2
#pragma unroll
    for (int e = 0; e < 4; e++) {
        int idx = t + e * 1024;                // n1
        float sgn = ((row + idx) & 1) ? -scale : scale;
        g_img[base + idx] = s0[idx].x * sgn;
    }
}

// ---------------- conv 3x3 stride 3 + bias + BN + PReLU (operates on TRANSPOSED image) ----------------
// Uses transposed weights w^T[dy][dx] = w[dx][dy] so the result equals the transposed
// original conv output (square images at every stage).
__global__ void conv_bn_prelu(const float* __restrict__ in, float* __restrict__ out,
                              int Win, int Wout, int Hout,
                              const float* __restrict__ cw, const float* __restrict__ cb,
                              const float* __restrict__ bg, const float* __restrict__ bb,
                              const float* __restrict__ bm, const float* __restrict__ bv,
                              const float* __restrict__ pa, int layer)
{
    int j = blockIdx.x * blockDim.x + threadIdx.x;
    int i = blockIdx.y * blockDim.y + threadIdx.y;
    if (i >= Hout || j >= Wout) return;
    const float* wb = cw + layer * 9;
    float w[9];
#pragma unroll
    for (int dy = 0; dy < 3; dy++)
#pragma unroll
        for (int dx = 0; dx < 3; dx++)
            w[dy * 3 + dx] = __ldg(&wb[dx * 3 + dy]);   // transposed weight
    const float* r0 = in + (size_t)(3 * i) * Win + 3 * j;
    float acc = 0.0f;
#pragma unroll
    for (int dy = 0; dy < 3; dy++)
#pragma unroll
        for (int dx = 0; dx < 3; dx++)
            acc = fmaf(r0[(size_t)dy * Win + dx], w[dy * 3 + dx], acc);
    acc += __ldg(&cb[layer]);
    float rs = rsqrtf(__ldg(&bv[layer]) + 1e-5f);
    float gg = __ldg(&bg[layer]);
    float sc = gg * rs;
    float sh = __ldg(&bb[layer]) - gg * __ldg(&bm[layer]) * rs;
    acc = fmaf(acc, sc, sh);
    float al = __ldg(&pa[layer]);
    out[(size_t)i * Wout + j] = (acc >= 0.0f) ? acc : al * acc;
}

// ---------------- head: flatten(un-transpose) + FC5 + LayerNorm + PReLU + FC6 ----------------
__global__ void head_kernel(const float* __restrict__ x5T,
                            const float* __restrict__ fc5w, const float* __restrict__ fc5b,
                            const float* __restrict__ lng,  const float* __restrict__ lnb,
                            const float* __restrict__ p5a,
                            const float* __restrict__ fc6w, const float* __restrict__ fc6b,
                            float* __restrict__ out)
{
    __shared__ float xv[256];
    __shared__ float h[82];
    __shared__ float mu_s, rstd_s;
    int t = threadIdx.x;
    // original flatten v = i*16 + j  ->  transposed buffer x5T[j*16 + i]
    for (int v = t; v < 256; v += blockDim.x) {
        int i = v >> 4, j = v & 15;
        xv[v] = x5T[j * 16 + i];
    }
    __syncthreads();
    for (int o = t; o < 82; o += blockDim.x) {
        float acc = fc5b[o];
        for (int v = 0; v < 256; v++)
            acc = fmaf(xv[v], fc5w[v * 82 + o], acc);
        h[o] = acc;
    }
    __syncthreads();
    if (t == 0) {
        float mu = 0.0f;
        for (int o = 0; o < 82; o++) mu += h[o];
        mu *= (1.0f / 82.0f);
        float var = 0.0f;
        for (int o = 0; o < 82; o++) { float dd = h[o] - mu; var = fmaf(dd, dd, var); }
        var *= (1.0f / 82.0f);
        mu_s = mu;
        rstd_s = rsqrtf(var + 1e-5f);
    }
    __syncthreads();
    if (t < 5) {
        float alpha = p5a[0];
        float acc = fc6b[t];
        for (int k = 0; k < 82; k++) {
            float v = (h[k] - mu_s) * rstd_s * lng[k] + lnb[k];
            v = (v >= 0.0f) ? v : alpha * v;
            acc = fmaf(v, fc6w[k * 5 + t], acc);
        }
        out[t] = acc;
    }
}

// ---------------- launch ----------------
extern "C" void kernel_launch(void* const* d_in, const int* in_sizes, int n_in,
                              void* d_out, int out_size)
{
    const float* xr    = (const float*)d_in[0];
    const float* xi    = (const float*)d_in[1];
    const float* mk    = (const float*)d_in[2];
    const float* pk    = (const float*)d_in[3];
    const float* convw = (const float*)d_in[4];
    const float* convb = (const float*)d_in[5];
    const float* bng   = (const float*)d_in[6];
    const float* bnb   = (const float*)d_in[7];
    const float* bnm   = (const float*)d_in[8];
    const float* bnv   = (const float*)d_in[9];
    const float* pra   = (const float*)d_in[10];
    const float* fc5w  = (const float*)d_in[11];
    const float* fc5b  = (const float*)d_in[12];
    const float* lng   = (const float*)d_in[13];
    const float* lnb   = (const float*)d_in[14];
    const float* p5a   = (const float*)d_in[15];
    const float* fc6w  = (const float*)d_in[16];
    const float* fc6b  = (const float*)d_in[17];
    float* out = (float*)d_out;

    cudaFuncSetAttribute(fft_pass1, cudaFuncAttributeMaxDynamicSharedMemorySize, 65536);
    cudaFuncSetAttribute(fft_pass2, cudaFuncAttributeMaxDynamicSharedMemorySize, 65536);

    float *img, *c1, *c2, *c3, *c4, *c5;
    cudaGetSymbolAddress((void**)&img, g_img);
    cudaGetSymbolAddress((void**)&c1,  g_c1);
    cudaGetSymbolAddress((void**)&c2,  g_c2);
    cudaGetSymbolAddress((void**)&c3,  g_c3);
    cudaGetSymbolAddress((void**)&c4,  g_c4);
    cudaGetSymbolAddress((void**)&c5,  g_c5);

    twiddle_init<<<1, 1024>>>();
    fft_pass1<<<4096, 1024, 65536>>>(xr, xi, mk, pk);
    transpose_c<<<dim3(128, 128), dim3(32, 8)>>>();
    fft_pass2<<<4096, 1024, 65536>>>();

    dim3 cb(32, 8);
    conv_bn_prelu<<<dim3((1365 + 31) / 32, (1365 + 7) / 8), cb>>>(img, c1, 4096, 1365, 1365,
        convw, convb, bng, bnb, bnm, bnv, pra, 0);
    conv_bn_prelu<<<dim3((455 + 31) / 32, (455 + 7) / 8), cb>>>(c1, c2, 1365, 455, 455,
        convw, convb, bng, bnb, bnm, bnv, pra, 1);
    conv_bn_prelu<<<dim3((151 + 31) / 32, (151 + 7) / 8), cb>>>(c2, c3, 455, 151, 151,
        convw, convb, bng, bnb, bnm, bnv, pra, 2);
    conv_bn_prelu<<<dim3((50 + 31) / 32, (50 + 7) / 8), cb>>>(c3, c4, 151, 50, 50,
        convw, convb, bng, bnb, bnm, bnv, pra, 3);
    conv_bn_prelu<<<dim3(1, 2), cb>>>(c4, c5, 50, 16, 16,
        convw, convb, bng, bnb, bnm, bnv, pra, 4);

    head_kernel<<<1, 128>>>(c5, fc5w, fc5b, lng, lnb, p5a, fc6w, fc6b, out);
}